// round 6
// baseline (speedup 1.0000x reference)
#include <cuda_runtime.h>

// newQConv1D analytic form (exact closed form of the quantum circuit):
//   out[b,c,l] = cos(theta[c][0]) * PROD_{q=1..9} cos(col_q)
//              - sin(theta[c][0]) * sin(col_0)*sin(col_1)
// col_{ck*5+k} = x[b, ck, l+k].  B=16, IN_CH=2, L=1024, K=5, OUT_CH=8, out_len=1020.
//
// Derivation: only theta_0 survives the Z0 expectation (RYs on qubits 1..9
// conjugate-cancel); the CNOT ring is GF(2)-linear, its MSB-output parity
// gives <Z0> = prod_{q=1..9} cos(x_q), and pi^{-1}(1<<9)=0x300 gives
// <X0> = sin(x_0) sin(x_1) on the product state. MUFU trig on N(0,1) args
// is ~2^-21 accurate -> rel_err ~5e-7, far under the 1e-3 gate.
//
// Final config (floor-bound at harness launch overhead): 16 blocks x 256
// threads, 4 outputs/thread via float4, no __syncthreads/smem — each warp's
// lanes 0-7 compute cos/sin(theta_c0) and broadcast via __shfl_sync, so the
// theta and x L2 latencies fully overlap on a sync-free critical path.

#define QL 1024
#define QOUT_LEN 1020
#define QOUT_CH 8

__global__ __launch_bounds__(256) void qconv1d_analytic_final(
    const float* __restrict__ x,       // [16, 2, 1024]
    const float* __restrict__ thetas,  // [8, 10]
    float* __restrict__ out)           // [16, 8, 1020]
{
    const int b    = blockIdx.x;            // 0..15
    const int t    = threadIdx.x;           // 0..255
    const int lane = t & 31;
    const int l0   = t << 2;                // 0,4,...,1020
    const bool act = (l0 < QOUT_LEN);       // thread 255 idle (would OOB)

    // Issue x loads and per-warp theta load back-to-back: latencies overlap.
    float4 A0, A1, B0, B1;
    if (act) {
        const float* xa = x + (size_t)b * 2 * QL + l0;
        A0 = *(const float4*)(xa);
        A1 = *(const float4*)(xa + 4);
        B0 = *(const float4*)(xa + QL);
        B1 = *(const float4*)(xa + QL + 4);
    }

    float myct = 0.f, mynst = 0.f;
    if (lane < QOUT_CH) {
        float s;
        __sincosf(thetas[lane * 10], &s, &myct);
        mynst = -s;                          // pre-negate: epilogue is pure FMA
    }

    if (act) {
        float a[8]  = {A0.x, A0.y, A0.z, A0.w, A1.x, A1.y, A1.z, A1.w};
        float bv[8] = {B0.x, B0.y, B0.z, B0.w, B1.x, B1.y, B1.z, B1.w};

        // Needed trig: sin(a[0..4]), cos(a[1..7]), cos(b[0..7]) -> 20 MUFU.
        float sa[5], ca[8], cb[8];
        sa[0] = __sinf(a[0]);
#pragma unroll
        for (int i = 1; i < 5; i++) __sincosf(a[i], &sa[i], &ca[i]);
#pragma unroll
        for (int i = 5; i < 8; i++) ca[i] = __cosf(a[i]);
#pragma unroll
        for (int i = 0; i < 8; i++) cb[i] = __cosf(bv[i]);

        float P[4], Q[4];
#pragma unroll
        for (int i = 0; i < 4; i++) {
            float pa = (ca[i + 1] * ca[i + 2]) * (ca[i + 3] * ca[i + 4]);
            float pb = (cb[i] * cb[i + 1]) * (cb[i + 2] * cb[i + 3]);
            P[i] = pa * pb * cb[i + 4];
            Q[i] = sa[i] * sa[i + 1];
        }

        float* o = out + (size_t)b * QOUT_CH * QOUT_LEN + l0;
#pragma unroll
        for (int c = 0; c < QOUT_CH; c++) {
            float ct = __shfl_sync(0xffffffffu, myct, c);
            float ns = __shfl_sync(0xffffffffu, mynst, c);
            float4 r;
            r.x = fmaf(ct, P[0], ns * Q[0]);
            r.y = fmaf(ct, P[1], ns * Q[1]);
            r.z = fmaf(ct, P[2], ns * Q[2]);
            r.w = fmaf(ct, P[3], ns * Q[3]);
            *(float4*)(o + (size_t)c * QOUT_LEN) = r;  // 4080B stride, 16B aligned
        }
    } else {
        // Keep the warp converged for the shfl exchanges above.
#pragma unroll
        for (int c = 0; c < QOUT_CH; c++) {
            __shfl_sync(0xffffffffu, myct, c);
            __shfl_sync(0xffffffffu, mynst, c);
        }
    }
}

extern "C" void kernel_launch(void* const* d_in, const int* in_sizes, int n_in,
                              void* d_out, int out_size) {
    const float* x      = (const float*)d_in[0];  // 16*2*1024
    const float* thetas = (const float*)d_in[1];  // 8*10
    // d_in[2] = entangle matrix: unused (folded analytically)
    float* out = (float*)d_out;                   // 16*8*1020

    qconv1d_analytic_final<<<16, 256>>>(x, thetas, out);
}

// round 7
// speedup vs baseline: 1.3478x; 1.3478x over previous
#include <cuda_runtime.h>

// newQConv1D analytic form (exact closed form of the quantum circuit):
//   out[b,c,l] = cos(theta[c][0]) * PROD_{q=1..9} cos(col_q)
//              - sin(theta[c][0]) * sin(col_0)*sin(col_1)
// col_{ck*5+k} = x[b, ck, l+k].  B=16, IN_CH=2, L=1024, K=5, OUT_CH=8, out_len=1020.
//
// Derivation: only theta_0 survives the Z0 expectation (RYs on qubits 1..9
// conjugate-cancel); the CNOT ring is GF(2)-linear, its MSB-output parity
// gives <Z0> = prod_{q=1..9} cos(x_q), and pi^{-1}(1<<9)=0x300 gives
// <X0> = sin(x_0) sin(x_1) on the product state. MUFU trig on N(0,1) args
// is ~2^-21 accurate -> rel_err ~5e-7, far under the 1e-3 gate.
//
// v5 config (measured floor: 6.656us e2e / 4.58us kernel): 16 blocks x 256
// threads, 4 outputs/thread via float4, no __syncthreads/smem. Each warp's
// lanes 0-7 compute cos/sin(theta_c0) and broadcast via __shfl_sync kept
// WARP-UNIFORM (outside the act-predicate) so ptxas predicates the stores
// instead of emitting a BSSY/BSYNC diverge region around the MUFU chain
// (the R5 regression showed that costs +2.4us).

#define QL 1024
#define QOUT_LEN 1020
#define QOUT_CH 8

__global__ __launch_bounds__(256) void qconv1d_analytic_v5(
    const float* __restrict__ x,       // [16, 2, 1024]
    const float* __restrict__ thetas,  // [8, 10]
    float* __restrict__ out)           // [16, 8, 1020]
{
    const int b    = blockIdx.x;            // 0..15
    const int t    = threadIdx.x;           // 0..255
    const int lane = t & 31;
    const int l0   = t << 2;                // 0,4,...,1020
    const bool act = (l0 < QOUT_LEN);       // thread 255 idle

    // ---- issue x loads and per-warp theta load together (overlapping) ----
    float4 A0, A1, B0, B1;
    if (act) {
        const float* xa = x + (size_t)b * 2 * QL + l0;
        A0 = *(const float4*)(xa);
        A1 = *(const float4*)(xa + 4);
        B0 = *(const float4*)(xa + QL);
        B1 = *(const float4*)(xa + QL + 4);
    } else {
        A0 = A1 = B0 = B1 = make_float4(0.f, 0.f, 0.f, 0.f);
    }

    float myct = 0.f, myst = 0.f;
    if (lane < QOUT_CH) {
        __sincosf(thetas[lane * 10], &myst, &myct);
    }

    float a[8]  = {A0.x, A0.y, A0.z, A0.w, A1.x, A1.y, A1.z, A1.w};
    float bv[8] = {B0.x, B0.y, B0.z, B0.w, B1.x, B1.y, B1.z, B1.w};

    // Needed trig: sin(a[0..4]), cos(a[1..7]), cos(b[0..7])  -> 20 MUFU ops.
    float sa[5], ca[8], cb[8];
    sa[0] = __sinf(a[0]);
#pragma unroll
    for (int i = 1; i < 5; i++) __sincosf(a[i], &sa[i], &ca[i]);
#pragma unroll
    for (int i = 5; i < 8; i++) ca[i] = __cosf(a[i]);
#pragma unroll
    for (int i = 0; i < 8; i++) cb[i] = __cosf(bv[i]);

    float P[4], Q[4];
#pragma unroll
    for (int i = 0; i < 4; i++) {
        float pa = (ca[i + 1] * ca[i + 2]) * (ca[i + 3] * ca[i + 4]);
        float pb = (cb[i] * cb[i + 1]) * (cb[i + 2] * cb[i + 3]);
        P[i] = pa * pb * cb[i + 4];
        Q[i] = sa[i] * sa[i + 1];
    }

    float* o = out + (size_t)b * QOUT_CH * QOUT_LEN + l0;
#pragma unroll
    for (int c = 0; c < QOUT_CH; c++) {
        float ct = __shfl_sync(0xffffffffu, myct, c);
        float st = __shfl_sync(0xffffffffu, myst, c);
        if (act) {
            float4 r;
            r.x = fmaf(ct, P[0], -st * Q[0]);
            r.y = fmaf(ct, P[1], -st * Q[1]);
            r.z = fmaf(ct, P[2], -st * Q[2]);
            r.w = fmaf(ct, P[3], -st * Q[3]);
            *(float4*)(o + (size_t)c * QOUT_LEN) = r;  // 4080B stride, 16B aligned
        }
    }
}

extern "C" void kernel_launch(void* const* d_in, const int* in_sizes, int n_in,
                              void* d_out, int out_size) {
    const float* x      = (const float*)d_in[0];  // 16*2*1024
    const float* thetas = (const float*)d_in[1];  // 8*10
    // d_in[2] = entangle matrix: unused (folded analytically)
    float* out = (float*)d_out;                   // 16*8*1020

    qconv1d_analytic_v5<<<16, 256>>>(x, thetas, out);
}